// round 2
// baseline (speedup 1.0000x reference)
#include <cuda_runtime.h>

#define B 8
#define HID 192
#define FEAT 512
#define CATN 576
#define PIECES 64
#define HW 65536   // 256*256
#define PLANE3 (3*HW)

// Scratch (allocation-free rule: __device__ globals)
__device__ float  g_outs[4 * B * HID];          // outputs of the 4 projections
__device__ float2 g_table[B * 9 * PIECES];      // per (b, set*3+c): {prefix/sum, param/sum}

// ---------------------------------------------------------------------------
// Kernel A: 4 stacked projections, fc2(relu(fc1(feat))). One block per k.
// ---------------------------------------------------------------------------
__global__ void proj_kernel(const float* __restrict__ f_feat,
                            const float* __restrict__ b_feat,
                            const float* __restrict__ w1,
                            const float* __restrict__ b1,
                            const float* __restrict__ w2,
                            const float* __restrict__ b2) {
    int k = blockIdx.x;      // 0..3  (inputs: f, b, f, b)
    int o = threadIdx.x;     // 0..191
    __shared__ float s_feat[B][FEAT];
    __shared__ float s_h[B][HID];

    const float* feat = (k & 1) ? b_feat : f_feat;
    for (int i = o; i < B * FEAT; i += HID)
        s_feat[i >> 9][i & 511] = feat[i];
    __syncthreads();

    float acc[B];
    #pragma unroll
    for (int b = 0; b < B; b++) acc[b] = b1[k * HID + o];
    const float* W1 = w1 + k * FEAT * HID;
    #pragma unroll 4
    for (int i = 0; i < FEAT; i++) {
        float w = W1[i * HID + o];
        #pragma unroll
        for (int b = 0; b < B; b++) acc[b] = fmaf(s_feat[b][i], w, acc[b]);
    }
    #pragma unroll
    for (int b = 0; b < B; b++) s_h[b][o] = fmaxf(acc[b], 0.0f);
    __syncthreads();

    #pragma unroll
    for (int b = 0; b < B; b++) acc[b] = b2[k * HID + o];
    const float* W2 = w2 + k * HID * HID;
    #pragma unroll 4
    for (int i = 0; i < HID; i++) {
        float w = W2[i * HID + o];
        #pragma unroll
        for (int b = 0; b < B; b++) acc[b] = fmaf(s_h[b][i], w, acc[b]);
    }
    #pragma unroll
    for (int b = 0; b < B; b++) g_outs[(k * B + b) * HID + o] = acc[b];
}

// ---------------------------------------------------------------------------
// Kernel B: final FC on cat([param_f, param_b, param_s]) + build lookup tables.
// Single block, 192 threads.
// ---------------------------------------------------------------------------
__global__ void fc_table_kernel(const float* __restrict__ w1,
                                const float* __restrict__ b1,
                                const float* __restrict__ w2,
                                const float* __restrict__ b2) {
    int o = threadIdx.x;     // 0..191
    __shared__ float s_cat[B][CATN];
    __shared__ float s_h[B][HID];
    __shared__ float s_pall[B][HID];

    for (int idx = o; idx < B * HID; idx += HID) {
        int b = idx / HID, q = idx % HID;
        s_cat[b][q]           = g_outs[(0 * B + b) * HID + q];               // param_f
        s_cat[b][HID + q]     = g_outs[(1 * B + b) * HID + q];               // param_b
        s_cat[b][2 * HID + q] = g_outs[(2 * B + b) * HID + q]
                              + g_outs[(3 * B + b) * HID + q];               // param_s
    }
    __syncthreads();

    float acc[B];
    #pragma unroll
    for (int b = 0; b < B; b++) acc[b] = b1[o];
    #pragma unroll 4
    for (int i = 0; i < CATN; i++) {
        float w = w1[i * HID + o];
        #pragma unroll
        for (int b = 0; b < B; b++) acc[b] = fmaf(s_cat[b][i], w, acc[b]);
    }
    #pragma unroll
    for (int b = 0; b < B; b++) s_h[b][o] = fmaxf(acc[b], 0.0f);
    __syncthreads();

    #pragma unroll
    for (int b = 0; b < B; b++) acc[b] = b2[o];
    #pragma unroll 4
    for (int i = 0; i < HID; i++) {
        float w = w2[i * HID + o];
        #pragma unroll
        for (int b = 0; b < B; b++) acc[b] = fmaf(s_h[b][i], w, acc[b]);
    }
    #pragma unroll
    for (int b = 0; b < B; b++) s_pall[b][o] = acc[b];
    __syncthreads();

    // Build tables: 72 groups = set(3) * b(8) * c(3)
    if (o < 72) {
        int set = o / 24;
        int b   = (o % 24) / 3;
        int c   = o % 3;
        const float* p;
        if (set == 0)      p = &s_pall[b][c * PIECES];                    // param (fc output)
        else if (set == 1) p = &g_outs[(0 * B + b) * HID + c * PIECES];   // param_f
        else               p = &g_outs[(1 * B + b) * HID + c * PIECES];   // param_b
        float sum = 0.0f;
        for (int i = 0; i < PIECES; i++) sum += p[i];
        float inv = 1.0f / (sum + 1e-30f);
        float pref = 0.0f;
        float2* t = &g_table[(b * 9 + set * 3 + c) * PIECES];
        for (int i = 0; i < PIECES; i++) {
            t[i] = make_float2(pref * inv, p[i] * inv);
            pref += p[i];
        }
    }
}

// ---------------------------------------------------------------------------
// Kernel C: streaming render. Each block owns one batch's tables in smem.
// grid = 8 batches * 64 tiles, block = 256 threads, 4 pixels/thread (float4).
// ---------------------------------------------------------------------------
__device__ __forceinline__ float evalp(float v, const float2* __restrict__ tab) {
    float s = v * 64.0f;
    int k = (int)s;
    k = min(k, 63);
    float frac = s - (float)k;
    float2 e = tab[k];
    return fmaf(frac, e.y, e.x);
}

__device__ __forceinline__ float4 eval4(float4 v, const float2* __restrict__ tab) {
    return make_float4(evalp(v.x, tab), evalp(v.y, tab), evalp(v.z, tab), evalp(v.w, tab));
}

__global__ __launch_bounds__(256) void render_kernel(const float* __restrict__ x,
                                                     float* __restrict__ out) {
    __shared__ float2 sh[9 * PIECES];
    int b    = blockIdx.x >> 6;          // 64 tiles per batch
    int tile = blockIdx.x & 63;
    int t    = threadIdx.x;

    for (int i = t; i < 9 * PIECES; i += 256) sh[i] = g_table[b * 9 * PIECES + i];
    __syncthreads();

    int off = tile * 1024 + t * 4;       // offset within a [H,W] plane (floats)
    const float* xb = x + b * PLANE3;

    float4 v0 = *(const float4*)(xb + 0 * HW + off);
    float4 v1 = *(const float4*)(xb + 1 * HW + off);
    float4 v2 = *(const float4*)(xb + 2 * HW + off);

    float4 g;
    g.x = fmaf(0.114f, v2.x, fmaf(0.587f, v1.x, 0.299f * v0.x));
    g.y = fmaf(0.114f, v2.y, fmaf(0.587f, v1.y, 0.299f * v0.y));
    g.z = fmaf(0.114f, v2.z, fmaf(0.587f, v1.z, 0.299f * v0.z));
    g.w = fmaf(0.114f, v2.w, fmaf(0.587f, v1.w, 0.299f * v0.w));

    // out tensor 0: _cf(x, param_all) — per-channel input
    float* o0 = out + 0 * (B * PLANE3) + b * PLANE3 + off;
    *(float4*)(o0 + 0 * HW) = eval4(v0, &sh[0 * PIECES]);
    *(float4*)(o0 + 1 * HW) = eval4(v1, &sh[1 * PIECES]);
    *(float4*)(o0 + 2 * HW) = eval4(v2, &sh[2 * PIECES]);

    // out tensor 1: _cf(gray, param_f)
    float* o1 = out + 1 * (B * PLANE3) + b * PLANE3 + off;
    *(float4*)(o1 + 0 * HW) = eval4(g, &sh[3 * PIECES]);
    *(float4*)(o1 + 1 * HW) = eval4(g, &sh[4 * PIECES]);
    *(float4*)(o1 + 2 * HW) = eval4(g, &sh[5 * PIECES]);

    // out tensor 2: _cf(gray, param_b)
    float* o2 = out + 2 * (B * PLANE3) + b * PLANE3 + off;
    *(float4*)(o2 + 0 * HW) = eval4(g, &sh[6 * PIECES]);
    *(float4*)(o2 + 1 * HW) = eval4(g, &sh[7 * PIECES]);
    *(float4*)(o2 + 2 * HW) = eval4(g, &sh[8 * PIECES]);
}

// ---------------------------------------------------------------------------
extern "C" void kernel_launch(void* const* d_in, const int* in_sizes, int n_in,
                              void* d_out, int out_size) {
    const float* x        = (const float*)d_in[0];   // [8,3,256,256]
    const float* f_feat   = (const float*)d_in[1];   // [8,512]
    const float* b_feat   = (const float*)d_in[2];   // [8,512]
    const float* proj_w1  = (const float*)d_in[3];   // [4,512,192]
    const float* proj_b1  = (const float*)d_in[4];   // [4,192]
    const float* proj_w2  = (const float*)d_in[5];   // [4,192,192]
    const float* proj_b2  = (const float*)d_in[6];   // [4,192]
    const float* fc_w1    = (const float*)d_in[7];   // [576,192]
    const float* fc_b1    = (const float*)d_in[8];   // [192]
    const float* fc_w2    = (const float*)d_in[9];   // [192,192]
    const float* fc_b2    = (const float*)d_in[10];  // [192]
    float* out = (float*)d_out;

    proj_kernel<<<4, 192>>>(f_feat, b_feat, proj_w1, proj_b1, proj_w2, proj_b2);
    fc_table_kernel<<<1, 192>>>(fc_w1, fc_b1, fc_w2, fc_b2);
    render_kernel<<<B * 64, 256>>>(x, out);
}

// round 4
// speedup vs baseline: 3.1251x; 3.1251x over previous
#include <cuda_runtime.h>

#define B 8
#define HID 192
#define FEAT 512
#define CATN 576
#define PIECES 64
#define HW 65536   // 256*256
#define PLANE3 (3*HW)

// Scratch (__device__ globals: allocation-free rule)
__device__ float  g_h1[4 * B * HID];       // relu(feat @ w1 + b1) for 4 projections
__device__ float  g_cat[B * CATN];         // [param_f | param_b | param_s]
__device__ float  g_h2[B * HID];           // relu(cat @ fc_w1 + fc_b1)
__device__ float  g_param[B * HID];        // final fc output
__device__ float2 g_table[B * 9 * PIECES]; // per (b, set*3+c): {prefix/sum, param/sum}

__device__ __forceinline__ float warp_sum(float v) {
    #pragma unroll
    for (int m = 16; m > 0; m >>= 1) v += __shfl_xor_sync(0xffffffffu, v, m);
    return v;
}

// ---------------------------------------------------------------------------
// K1: projection layer 1. One warp per (k, o). grid=96x256 (8 warps/block,
// 24 blocks per k -> k constant per block). Lanes split the 512-dim reduction.
// ---------------------------------------------------------------------------
__global__ __launch_bounds__(256) void proj_l1(const float* __restrict__ f_feat,
                                               const float* __restrict__ b_feat,
                                               const float* __restrict__ w1,
                                               const float* __restrict__ b1) {
    __shared__ float s_feat[B][FEAT];
    int tid  = threadIdx.x;
    int l    = tid & 31;
    int wg   = blockIdx.x * 8 + (tid >> 5);   // 0..767
    int k    = wg / HID;
    int o    = wg % HID;

    const float* feat = (k & 1) ? b_feat : f_feat;
    for (int i = tid; i < B * FEAT; i += 256)
        s_feat[i >> 9][i & 511] = feat[i];
    __syncthreads();

    float acc[B];
    #pragma unroll
    for (int b = 0; b < B; b++) acc[b] = 0.0f;
    const float* W = w1 + k * FEAT * HID + o;
    #pragma unroll
    for (int t = 0; t < 16; t++) {
        int i = l + 32 * t;
        float w = W[i * HID];
        #pragma unroll
        for (int b = 0; b < B; b++) acc[b] = fmaf(s_feat[b][i], w, acc[b]);
    }
    #pragma unroll
    for (int b = 0; b < B; b++) acc[b] = warp_sum(acc[b]);
    if (l < B)
        g_h1[(k * B + l) * HID + o] = fmaxf(acc[l] + b1[k * HID + o], 0.0f);
}

// ---------------------------------------------------------------------------
// K2: projection layer 2 + build cat. One warp per (sec, o), sec in {0,1,2};
// sec==2 computes proj2 + proj3 (param_s). grid=72x256 (24 blocks per sec).
// ---------------------------------------------------------------------------
__global__ __launch_bounds__(256) void proj_l2(const float* __restrict__ w2,
                                               const float* __restrict__ b2) {
    __shared__ float s_h[2][B][HID];
    int tid = threadIdx.x;
    int l   = tid & 31;
    int wg  = blockIdx.x * 8 + (tid >> 5);    // 0..575
    int sec = wg / HID;                       // 0,1,2
    int o   = wg % HID;

    // stage h1 for this section (sec==2 needs projections 2 and 3)
    int k0 = sec;
    for (int i = tid; i < B * HID; i += 256)
        s_h[0][i / HID][i % HID] = g_h1[(k0 * B) * HID + i];
    if (sec == 2)
        for (int i = tid; i < B * HID; i += 256)
            s_h[1][i / HID][i % HID] = g_h1[(3 * B) * HID + i];
    __syncthreads();

    float acc[B];
    #pragma unroll
    for (int b = 0; b < B; b++) acc[b] = 0.0f;
    const float* W0 = w2 + k0 * HID * HID + o;
    #pragma unroll
    for (int t = 0; t < 6; t++) {
        int i = l + 32 * t;
        float w = W0[i * HID];
        #pragma unroll
        for (int b = 0; b < B; b++) acc[b] = fmaf(s_h[0][b][i], w, acc[b]);
    }
    if (sec == 2) {
        const float* W1 = w2 + 3 * HID * HID + o;
        #pragma unroll
        for (int t = 0; t < 6; t++) {
            int i = l + 32 * t;
            float w = W1[i * HID];
            #pragma unroll
            for (int b = 0; b < B; b++) acc[b] = fmaf(s_h[1][b][i], w, acc[b]);
        }
    }
    #pragma unroll
    for (int b = 0; b < B; b++) acc[b] = warp_sum(acc[b]);
    if (l < B) {
        float bias = (sec == 2) ? (b2[2 * HID + o] + b2[3 * HID + o]) : b2[sec * HID + o];
        g_cat[l * CATN + sec * HID + o] = acc[l] + bias;
    }
}

// ---------------------------------------------------------------------------
// K3: fc layer 1. One warp per (b, o). grid=192x256 (24 blocks per batch).
// ---------------------------------------------------------------------------
__global__ __launch_bounds__(256) void fc_l1(const float* __restrict__ w1,
                                             const float* __restrict__ b1) {
    __shared__ float s_cat[CATN];
    int tid = threadIdx.x;
    int l   = tid & 31;
    int wg  = blockIdx.x * 8 + (tid >> 5);    // 0..1535
    int b   = wg / HID;
    int o   = wg % HID;

    for (int i = tid; i < CATN; i += 256) s_cat[i] = g_cat[b * CATN + i];
    __syncthreads();

    float acc = 0.0f;
    const float* W = w1 + o;
    #pragma unroll
    for (int t = 0; t < 18; t++) {
        int i = l + 32 * t;
        acc = fmaf(s_cat[i], W[i * HID], acc);
    }
    acc = warp_sum(acc);
    if (l == 0) g_h2[b * HID + o] = fmaxf(acc + b1[o], 0.0f);
}

// ---------------------------------------------------------------------------
// K4: fc layer 2. One warp per (b, o). grid=192x256.
// ---------------------------------------------------------------------------
__global__ __launch_bounds__(256) void fc_l2(const float* __restrict__ w2,
                                             const float* __restrict__ b2) {
    __shared__ float s_h[HID];
    int tid = threadIdx.x;
    int l   = tid & 31;
    int wg  = blockIdx.x * 8 + (tid >> 5);
    int b   = wg / HID;
    int o   = wg % HID;

    for (int i = tid; i < HID; i += 256) s_h[i] = g_h2[b * HID + i];
    __syncthreads();

    float acc = 0.0f;
    const float* W = w2 + o;
    #pragma unroll
    for (int t = 0; t < 6; t++) {
        int i = l + 32 * t;
        acc = fmaf(s_h[i], W[i * HID], acc);
    }
    acc = warp_sum(acc);
    if (l == 0) g_param[b * HID + o] = acc + b2[o];
}

// ---------------------------------------------------------------------------
// K5: build 72 lookup tables. One warp per (set, b, c); warp-shuffle prefix
// scan over the 64 pieces (2 per lane). grid=9x256.
// ---------------------------------------------------------------------------
__global__ __launch_bounds__(256) void table_kernel() {
    int l   = threadIdx.x & 31;
    int grp = blockIdx.x * 8 + (threadIdx.x >> 5);   // 0..71
    int set = grp / 24;
    int b   = (grp % 24) / 3;
    int c   = grp % 3;

    const float* p;
    if (set == 0)      p = g_param + b * HID + c * PIECES;          // param (fc)
    else if (set == 1) p = g_cat + b * CATN + c * PIECES;           // param_f
    else               p = g_cat + b * CATN + HID + c * PIECES;     // param_b

    float v0 = p[2 * l];
    float v1 = p[2 * l + 1];
    float pair = v0 + v1;

    // inclusive scan of pair sums across lanes
    float inc = pair;
    #pragma unroll
    for (int d = 1; d < 32; d <<= 1) {
        float u = __shfl_up_sync(0xffffffffu, inc, d);
        if (l >= d) inc += u;
    }
    float total = __shfl_sync(0xffffffffu, inc, 31);
    float excl  = inc - pair;                       // prefix before index 2l
    float inv   = 1.0f / (total + 1e-30f);

    float2* t = &g_table[(b * 9 + set * 3 + c) * PIECES];
    t[2 * l]     = make_float2(excl * inv, v0 * inv);
    t[2 * l + 1] = make_float2((excl + v0) * inv, v1 * inv);
}

// ---------------------------------------------------------------------------
// K6: streaming render (unchanged from R2 — already near HBM floor).
// ---------------------------------------------------------------------------
__device__ __forceinline__ float evalp(float v, const float2* __restrict__ tab) {
    float s = v * 64.0f;
    int k = (int)s;
    k = min(k, 63);
    float frac = s - (float)k;
    float2 e = tab[k];
    return fmaf(frac, e.y, e.x);
}

__device__ __forceinline__ float4 eval4(float4 v, const float2* __restrict__ tab) {
    return make_float4(evalp(v.x, tab), evalp(v.y, tab), evalp(v.z, tab), evalp(v.w, tab));
}

__global__ __launch_bounds__(256) void render_kernel(const float* __restrict__ x,
                                                     float* __restrict__ out) {
    __shared__ float2 sh[9 * PIECES];
    int b    = blockIdx.x >> 6;
    int tile = blockIdx.x & 63;
    int t    = threadIdx.x;

    for (int i = t; i < 9 * PIECES; i += 256) sh[i] = g_table[b * 9 * PIECES + i];
    __syncthreads();

    int off = tile * 1024 + t * 4;
    const float* xb = x + b * PLANE3;

    float4 v0 = *(const float4*)(xb + 0 * HW + off);
    float4 v1 = *(const float4*)(xb + 1 * HW + off);
    float4 v2 = *(const float4*)(xb + 2 * HW + off);

    float4 g;
    g.x = fmaf(0.114f, v2.x, fmaf(0.587f, v1.x, 0.299f * v0.x));
    g.y = fmaf(0.114f, v2.y, fmaf(0.587f, v1.y, 0.299f * v0.y));
    g.z = fmaf(0.114f, v2.z, fmaf(0.587f, v1.z, 0.299f * v0.z));
    g.w = fmaf(0.114f, v2.w, fmaf(0.587f, v1.w, 0.299f * v0.w));

    float* o0 = out + 0 * (B * PLANE3) + b * PLANE3 + off;
    *(float4*)(o0 + 0 * HW) = eval4(v0, &sh[0 * PIECES]);
    *(float4*)(o0 + 1 * HW) = eval4(v1, &sh[1 * PIECES]);
    *(float4*)(o0 + 2 * HW) = eval4(v2, &sh[2 * PIECES]);

    float* o1 = out + 1 * (B * PLANE3) + b * PLANE3 + off;
    *(float4*)(o1 + 0 * HW) = eval4(g, &sh[3 * PIECES]);
    *(float4*)(o1 + 1 * HW) = eval4(g, &sh[4 * PIECES]);
    *(float4*)(o1 + 2 * HW) = eval4(g, &sh[5 * PIECES]);

    float* o2 = out + 2 * (B * PLANE3) + b * PLANE3 + off;
    *(float4*)(o2 + 0 * HW) = eval4(g, &sh[6 * PIECES]);
    *(float4*)(o2 + 1 * HW) = eval4(g, &sh[7 * PIECES]);
    *(float4*)(o2 + 2 * HW) = eval4(g, &sh[8 * PIECES]);
}

// ---------------------------------------------------------------------------
extern "C" void kernel_launch(void* const* d_in, const int* in_sizes, int n_in,
                              void* d_out, int out_size) {
    const float* x        = (const float*)d_in[0];
    const float* f_feat   = (const float*)d_in[1];
    const float* b_feat   = (const float*)d_in[2];
    const float* proj_w1  = (const float*)d_in[3];
    const float* proj_b1  = (const float*)d_in[4];
    const float* proj_w2  = (const float*)d_in[5];
    const float* proj_b2  = (const float*)d_in[6];
    const float* fc_w1    = (const float*)d_in[7];
    const float* fc_b1    = (const float*)d_in[8];
    const float* fc_w2    = (const float*)d_in[9];
    const float* fc_b2    = (const float*)d_in[10];
    float* out = (float*)d_out;

    proj_l1<<<96, 256>>>(f_feat, b_feat, proj_w1, proj_b1);
    proj_l2<<<72, 256>>>(proj_w2, proj_b2);
    fc_l1<<<192, 256>>>(fc_w1, fc_b1);
    fc_l2<<<192, 256>>>(fc_w2, fc_b2);
    table_kernel<<<9, 256>>>();
    render_kernel<<<B * 64, 256>>>(x, out);
}

// round 5
// speedup vs baseline: 3.2967x; 1.0549x over previous
#include <cuda_runtime.h>

#define B 8
#define HID 192
#define CATN 576
#define PIECES 64
#define HW 65536   // 256*256
#define PLANE3 (3*HW)
#define NBLK 148
#define NTHR 256

// ---------------- scratch (__device__ globals; allocation-free rule) --------
__device__ float  g_p1[4][4*B*HID];   // stage1 partials [isplit][(k*B+b)*HID+o]
__device__ float  g_p2[2][B*CATN];    // stage2 partials [isplit][b*CATN+sec*HID+o]
__device__ float  g_p3[3][B*HID];     // stage3 partials
__device__ float  g_p4[2][B*HID];     // stage4 partials
__device__ float2 g_table[B*9*PIECES];
__device__ unsigned g_count = 0;
__device__ volatile unsigned g_gen = 0;

// ---------------- software grid barrier (148 co-resident CTAs) --------------
__device__ __forceinline__ void grid_sync() {
    __syncthreads();
    if (threadIdx.x == 0) {
        __threadfence();                       // publish my stage's writes
        unsigned my = g_gen;
        if (atomicAdd(&g_count, 1u) == NBLK - 1u) {
            g_count = 0;
            __threadfence();
            g_gen = my + 1u;                   // release
        } else {
            while (g_gen == my) { }            // volatile spin
        }
        __threadfence();
    }
    __syncthreads();
}

// ---------------- coalesced GEMV partial-accumulate -------------------------
// W points at [ibase][obase] of a row-major [R][192] matrix. Warp w covers
// reduction sub-chunk [w*RB/8, ...). Lane l owns outputs obase + t*32 + l.
template<int RB, int NT>
__device__ __forceinline__ void gemv_acc(const float* __restrict__ W,
                                         const float* __restrict__ sX,  // [B][RB]
                                         float acc[NT][B]) {
    const int l = threadIdx.x & 31;
    const int w = threadIdx.x >> 5;
    const int CH = RB / 8;
    const float* Wp = W + (w * CH) * HID + l;
    const float* Xp = sX + w * CH;
    #pragma unroll 4
    for (int j = 0; j < CH; j++) {
        float wv[NT];
        #pragma unroll
        for (int t = 0; t < NT; t++) wv[t] = Wp[j * HID + t * 32];
        #pragma unroll
        for (int b = 0; b < B; b++) {
            float xv = Xp[b * RB + j];
            #pragma unroll
            for (int t = 0; t < NT; t++) acc[t][b] = fmaf(xv, wv[t], acc[t][b]);
        }
    }
}

// reduce 8 warps' partials in smem, write block partial (no bias) to global.
template<int NT>
__device__ __forceinline__ void store_partials(float acc[NT][B], float* s_part,
                                               float* __restrict__ dst,
                                               int strideB, int obase) {
    const int OT = NT * 32;
    const int l = threadIdx.x & 31;
    const int w = threadIdx.x >> 5;
    #pragma unroll
    for (int t = 0; t < NT; t++)
        #pragma unroll
        for (int b = 0; b < B; b++)
            s_part[(w * B + b) * OT + t * 32 + l] = acc[t][b];
    __syncthreads();
    for (int p = threadIdx.x; p < OT * B; p += NTHR) {
        int b = p / OT, o = p % OT;
        float s = 0.0f;
        #pragma unroll
        for (int w2 = 0; w2 < 8; w2++) s += s_part[(w2 * B + b) * OT + o];
        dst[b * strideB + obase + o] = s;
    }
}

// ---------------- render helpers --------------------------------------------
__device__ __forceinline__ float evalp(float v, const float2* __restrict__ tab) {
    float s = v * 64.0f;
    int k = (int)s;
    k = min(k, 63);
    float frac = s - (float)k;
    float2 e = tab[k];
    return fmaf(frac, e.y, e.x);
}
__device__ __forceinline__ float4 eval4(float4 v, const float2* __restrict__ tab) {
    return make_float4(evalp(v.x, tab), evalp(v.y, tab), evalp(v.z, tab), evalp(v.w, tab));
}

// ---------------- the whole problem, one kernel -----------------------------
__global__ __launch_bounds__(NTHR) void fused_kernel(
    const float* __restrict__ x,
    const float* __restrict__ f_feat, const float* __restrict__ b_feat,
    const float* __restrict__ pw1, const float* __restrict__ pb1,
    const float* __restrict__ pw2, const float* __restrict__ pb2,
    const float* __restrict__ fw1, const float* __restrict__ fb1,
    const float* __restrict__ fw2, const float* __restrict__ fb2,
    float* __restrict__ out)
{
    __shared__ __align__(16) float s_buf[9216];   // 36 KB, reused per stage
    float* s_x    = s_buf;            // X staging  (<=1536 floats)
    float* s_part = s_buf + 1536;     // warp partials (<=6144 floats)
    const int tid = threadIdx.x;
    const int blk = blockIdx.x;

    // ===== stage 1: proj layer1 partials. 32 blocks = 4k x 2oh x 4isplit ====
    if (blk < 32) {
        int k  = blk >> 3;
        int oh = (blk >> 2) & 1;
        int ip = blk & 3;
        const int RB = 128;
        int ibase = ip * RB, obase = oh * 96;
        const float* feat = (k & 1) ? b_feat : f_feat;
        for (int idx = tid; idx < B * RB; idx += NTHR)
            s_x[idx] = feat[(idx >> 7) * 512 + ibase + (idx & 127)];
        __syncthreads();
        float acc[3][B];
        #pragma unroll
        for (int t = 0; t < 3; t++)
            #pragma unroll
            for (int b = 0; b < B; b++) acc[t][b] = 0.0f;
        gemv_acc<128, 3>(pw1 + (k * 512 + ibase) * HID + obase, s_x, acc);
        store_partials<3>(acc, s_part, g_p1[ip] + (k * B) * HID, HID, obase);
    }
    grid_sync();

    // ===== stage 2: proj layer2 partials. 12 blocks = 3sec x 2oh x 2isplit ==
    if (blk < 12) {
        int sec = blk >> 2;
        int oh  = (blk >> 1) & 1;
        int ip  = blk & 1;
        const int RB = 96;
        int ibase = ip * RB, obase = oh * 96;
        int nk = (sec == 2) ? 2 : 1;
        for (int kk = 0; kk < nk; kk++) {
            int k = (sec == 2) ? (2 + kk) : sec;
            for (int idx = tid; idx < B * RB; idx += NTHR) {
                int b = idx / 96, i = idx % 96;
                int gi = (k * B + b) * HID + ibase + i;
                float v = g_p1[0][gi] + g_p1[1][gi] + g_p1[2][gi] + g_p1[3][gi]
                        + pb1[k * HID + ibase + i];
                s_x[kk * B * RB + idx] = fmaxf(v, 0.0f);
            }
        }
        __syncthreads();
        float acc[3][B];
        #pragma unroll
        for (int t = 0; t < 3; t++)
            #pragma unroll
            for (int b = 0; b < B; b++) acc[t][b] = 0.0f;
        int k0 = (sec == 2) ? 2 : sec;
        gemv_acc<96, 3>(pw2 + (k0 * HID + ibase) * HID + obase, s_x, acc);
        if (sec == 2)
            gemv_acc<96, 3>(pw2 + (3 * HID + ibase) * HID + obase, s_x + B * RB, acc);
        store_partials<3>(acc, s_part, g_p2[ip], CATN, sec * HID + obase);
    }
    grid_sync();

    // ===== stage 3: fc layer1 partials. 9 blocks = 3oq x 3isplit ============
    if (blk < 9) {
        int oq = blk / 3, ip = blk % 3;          // ip also = cat section
        const int RB = 192;
        int obase = oq * 64;
        for (int idx = tid; idx < B * RB; idx += NTHR) {
            int b = idx / 192, i = idx % 192;
            int gi = b * CATN + ip * HID + i;
            float v = g_p2[0][gi] + g_p2[1][gi];
            v += (ip < 2) ? pb2[ip * HID + i]
                          : (pb2[2 * HID + i] + pb2[3 * HID + i]);
            s_x[idx] = v;
        }
        __syncthreads();
        float acc[2][B];
        #pragma unroll
        for (int t = 0; t < 2; t++)
            #pragma unroll
            for (int b = 0; b < B; b++) acc[t][b] = 0.0f;
        gemv_acc<192, 2>(fw1 + (ip * HID) * HID + obase, s_x, acc);
        store_partials<2>(acc, s_part, g_p3[ip], HID, obase);
    }
    grid_sync();

    // ===== stage 4: fc layer2 partials. 4 blocks = 2oh x 2isplit ============
    if (blk < 4) {
        int oh = blk >> 1, ip = blk & 1;
        const int RB = 96;
        int ibase = ip * 96, obase = oh * 96;
        for (int idx = tid; idx < B * RB; idx += NTHR) {
            int b = idx / 96, i = idx % 96;
            int gi = b * HID + ibase + i;
            float v = g_p3[0][gi] + g_p3[1][gi] + g_p3[2][gi] + fb1[ibase + i];
            s_x[idx] = fmaxf(v, 0.0f);
        }
        __syncthreads();
        float acc[3][B];
        #pragma unroll
        for (int t = 0; t < 3; t++)
            #pragma unroll
            for (int b = 0; b < B; b++) acc[t][b] = 0.0f;
        gemv_acc<96, 3>(fw2 + ibase * HID + obase, s_x, acc);
        store_partials<3>(acc, s_part, g_p4[ip], HID, obase);
    }
    grid_sync();

    // ===== stage 5: build 72 lookup tables. 9 blocks x 8 warps ==============
    if (blk < 9) {
        int l = tid & 31;
        int grp = blk * 8 + (tid >> 5);          // 0..71
        int set = grp / 24;
        int b   = (grp % 24) / 3;
        int c   = grp % 3;
        int e0 = 2 * l, e1 = 2 * l + 1;
        float v0, v1;
        if (set == 0) {
            int gi = b * HID + c * 64;
            v0 = g_p4[0][gi + e0] + g_p4[1][gi + e0] + fb2[c * 64 + e0];
            v1 = g_p4[0][gi + e1] + g_p4[1][gi + e1] + fb2[c * 64 + e1];
        } else {
            int sec = set - 1;                   // param_f=sec0, param_b=sec1
            int gi = b * CATN + sec * HID + c * 64;
            v0 = g_p2[0][gi + e0] + g_p2[1][gi + e0] + pb2[sec * HID + c * 64 + e0];
            v1 = g_p2[0][gi + e1] + g_p2[1][gi + e1] + pb2[sec * HID + c * 64 + e1];
        }
        float pair = v0 + v1;
        float inc = pair;
        #pragma unroll
        for (int d = 1; d < 32; d <<= 1) {
            float u = __shfl_up_sync(0xffffffffu, inc, d);
            if (l >= d) inc += u;
        }
        float total = __shfl_sync(0xffffffffu, inc, 31);
        float excl  = inc - pair;
        float inv   = 1.0f / (total + 1e-30f);
        float2* t = &g_table[(b * 9 + set * 3 + c) * PIECES];
        t[e0] = make_float2(excl * inv, v0 * inv);
        t[e1] = make_float2((excl + v0) * inv, v1 * inv);
    }
    grid_sync();

    // ===== stage 6: streaming render, grid-stride float4 ====================
    float2* s_tab = (float2*)s_buf;              // 72 tables = 9216 floats
    for (int i = tid; i < B * 9 * PIECES; i += NTHR) s_tab[i] = g_table[i];
    __syncthreads();

    int gtid = blk * NTHR + tid;
    for (int p = gtid; p < B * HW / 4; p += NBLK * NTHR) {
        int b   = p >> 14;                       // HW/4 = 16384 per batch
        int off = (p & 16383) << 2;
        const float* xb = x + b * PLANE3 + off;
        float4 v0 = *(const float4*)(xb);
        float4 v1 = *(const float4*)(xb + HW);
        float4 v2 = *(const float4*)(xb + 2 * HW);

        float4 g;
        g.x = fmaf(0.114f, v2.x, fmaf(0.587f, v1.x, 0.299f * v0.x));
        g.y = fmaf(0.114f, v2.y, fmaf(0.587f, v1.y, 0.299f * v0.y));
        g.z = fmaf(0.114f, v2.z, fmaf(0.587f, v1.z, 0.299f * v0.z));
        g.w = fmaf(0.114f, v2.w, fmaf(0.587f, v1.w, 0.299f * v0.w));

        const float2* tb = s_tab + b * 9 * PIECES;

        float* o0 = out + b * PLANE3 + off;
        *(float4*)(o0)          = eval4(v0, tb + 0 * PIECES);
        *(float4*)(o0 + HW)     = eval4(v1, tb + 1 * PIECES);
        *(float4*)(o0 + 2 * HW) = eval4(v2, tb + 2 * PIECES);

        float* o1 = out + B * PLANE3 + b * PLANE3 + off;
        *(float4*)(o1)          = eval4(g, tb + 3 * PIECES);
        *(float4*)(o1 + HW)     = eval4(g, tb + 4 * PIECES);
        *(float4*)(o1 + 2 * HW) = eval4(g, tb + 5 * PIECES);

        float* o2 = out + 2 * B * PLANE3 + b * PLANE3 + off;
        *(float4*)(o2)          = eval4(g, tb + 6 * PIECES);
        *(float4*)(o2 + HW)     = eval4(g, tb + 7 * PIECES);
        *(float4*)(o2 + 2 * HW) = eval4(g, tb + 8 * PIECES);
    }
}

// ---------------------------------------------------------------------------
extern "C" void kernel_launch(void* const* d_in, const int* in_sizes, int n_in,
                              void* d_out, int out_size) {
    const float* x       = (const float*)d_in[0];
    const float* f_feat  = (const float*)d_in[1];
    const float* b_feat  = (const float*)d_in[2];
    const float* pw1     = (const float*)d_in[3];
    const float* pb1     = (const float*)d_in[4];
    const float* pw2     = (const float*)d_in[5];
    const float* pb2     = (const float*)d_in[6];
    const float* fw1     = (const float*)d_in[7];
    const float* fb1     = (const float*)d_in[8];
    const float* fw2     = (const float*)d_in[9];
    const float* fb2     = (const float*)d_in[10];
    float* out = (float*)d_out;

    fused_kernel<<<NBLK, NTHR>>>(x, f_feat, b_feat, pw1, pb1, pw2, pb2,
                                 fw1, fb1, fw2, fb2, out);
}